// round 6
// baseline (speedup 1.0000x reference)
#include <cuda_runtime.h>
#include <cuda_bf16.h>
#include <cstdint>
#include <cstddef>

// SRNN_multi: 2-layer spiking RNN, N=512, T=1000, H=128, DOUT=20.
//   k1: pre1[n,t,:] = x[n,t,:] @ Wi1^T + bi1 + bh1      (time-parallel GEMM)
//   k2: warp A: s1(t) = [pre1_t + s1@Wh1^T >= 1]        (layer-1 recurrence)
//       warp B: s2(t) = [s1@Wi2^T + b2 + s2@Wh2^T >= 1] (layer-2, ring-fed)
//   out = bo + (sum_t s2) @ Wo^T / T                    (telescoped epilogue)

#define NB   512
#define TS   1000
#define HD   128
#define DOUT 20
#define MTOT (NB * TS)

typedef unsigned long long ull;

// pre1 scratch, permuted: g_pre1[row*128 + lane*4 + q] = pre1[row][lane + 32*q]
// +512 pad so the 4-deep prefetch of the last row stays in bounds.
__device__ float g_pre1[(size_t)MTOT * HD + 512];

__device__ __forceinline__ ull pk2(float lo, float hi) {
    ull r; asm("mov.b64 %0, {%1, %2};" : "=l"(r) : "f"(lo), "f"(hi)); return r;
}
__device__ __forceinline__ float2 upk2(ull v) {
    float2 r; asm("mov.b64 {%0, %1}, %2;" : "=f"(r.x), "=f"(r.y) : "l"(v)); return r;
}
__device__ __forceinline__ void fma2(ull& d, ull a, ull b) {
    asm("fma.rn.f32x2 %0, %1, %2, %0;" : "+l"(d) : "l"(a), "l"(b));
}
__device__ __forceinline__ void add2(ull& d, ull a) {
    asm("add.rn.f32x2 %0, %1, %0;" : "+l"(d) : "l"(a));
}
__device__ __forceinline__ unsigned ld_acq(const unsigned* p) {
    unsigned v;
    asm volatile("ld.acquire.cta.u32 %0, [%1];" : "=r"(v) : "l"(p) : "memory");
    return v;
}
__device__ __forceinline__ void st_rel(unsigned* p, unsigned v) {
    asm volatile("st.release.cta.u32 [%0], %1;" :: "l"(p), "r"(v) : "memory");
}

// ---------------------------------------------------------------------------
// Kernel 1: pre1 = x @ Wi1^T + (bi1+bh1).
// 16000 CTAs x 256 thr; CTA = 32 rows; warp = 4 rows x 128 cols.
// x staged DUPLICATED in smem so one LDS.128 yields two packed-broadcast
// f32x2 multipliers (no pk2 MOVs in the main loop).
// ---------------------------------------------------------------------------
__global__ void __launch_bounds__(256, 2) k1_gemm(
    const float* __restrict__ x, const float* __restrict__ Wi1,
    const float* __restrict__ bi1, const float* __restrict__ bh1)
{
    extern __shared__ float sm[];
    float* ws  = sm;          // 16384 f: ws[k*128 + (j&31)*4 + (j>>5)] = Wi1[j*128+k]
    float* xs2 = sm + 16384;  // 8192 f:  per row 256 f, each x value stored twice

    const int tid = threadIdx.x, lane = tid & 31, warp = tid >> 5;

    // stage permuted Wi1 (vectorized reads)
    {
        const float4* Wg = (const float4*)Wi1;
        for (int i = tid; i < 4096; i += 256) {
            float4 v = Wg[i];
            int j = i >> 5, k = (i & 31) << 2;
            int jp = ((j & 31) << 2) + (j >> 5);
            ws[(k + 0) * 128 + jp] = v.x;
            ws[(k + 1) * 128 + jp] = v.y;
            ws[(k + 2) * 128 + jp] = v.z;
            ws[(k + 3) * 128 + jp] = v.w;
        }
    }
    // stage duplicated x: xs2[r*256 + 2k] = xs2[r*256 + 2k+1] = x[r][k]
    {
        const float4* xg = (const float4*)x + (size_t)blockIdx.x * 1024;
        float4* xd = (float4*)xs2;
        for (int i = tid; i < 1024; i += 256) {
            float4 v = xg[i];
            int r = i >> 5, c = i & 31;
            xd[r * 64 + 2 * c]     = make_float4(v.x, v.x, v.y, v.y);
            xd[r * 64 + 2 * c + 1] = make_float4(v.z, v.z, v.w, v.w);
        }
    }
    __syncthreads();

    const ull b01 = pk2(bi1[lane]      + bh1[lane],      bi1[lane + 32] + bh1[lane + 32]);
    const ull b23 = pk2(bi1[lane + 64] + bh1[lane + 64], bi1[lane + 96] + bh1[lane + 96]);

    ull a01[4], a23[4];
#pragma unroll
    for (int r = 0; r < 4; ++r) { a01[r] = b01; a23[r] = b23; }

    const ulonglong2* W = (const ulonglong2*)ws;
    const ulonglong2* X = (const ulonglong2*)xs2 + warp * 256;  // 4 rows x 64

#pragma unroll 4
    for (int kk = 0; kk < 64; ++kk) {          // k = 2*kk, 2*kk+1
        const ulonglong2 w0 = W[(2 * kk) * 32 + lane];
        const ulonglong2 w1 = W[(2 * kk + 1) * 32 + lane];
#pragma unroll
        for (int r = 0; r < 4; ++r) {
            const ulonglong2 xv = X[r * 64 + kk];  // {pk(xk,xk), pk(xk1,xk1)}
            fma2(a01[r], xv.x, w0.x); fma2(a23[r], xv.x, w0.y);
            fma2(a01[r], xv.y, w1.x); fma2(a23[r], xv.y, w1.y);
        }
    }

    const size_t rbase = (size_t)blockIdx.x * 32 + warp * 4;
#pragma unroll
    for (int r = 0; r < 4; ++r) {
        ulonglong2 o; o.x = a01[r]; o.y = a23[r];
        *(ulonglong2*)(g_pre1 + (rbase + r) * 128 + lane * 4) = o;
    }
}

// ---------------------------------------------------------------------------
// Kernel 2: recurrence. 128 CTAs x 256 thr.
// Warps 0-3: layer-1 producer for rows 0-3 of this CTA (s1 recurrence).
// Warps 4-7: layer-2 consumer (s2 recurrence + spike counts + epilogue).
// s1 masks flow through a 64-slot smem ring per row (release/acquire).
// ---------------------------------------------------------------------------

// software-pipelined sparse matvec: next weight column loaded before the
// current one is accumulated, hiding LDS latency behind adds + branch.
__device__ __forceinline__ void walk(
    const ulonglong2* __restrict__ W, ull m0, ull m1, int lane, ull& a, ull& b)
{
    if ((m0 | m1) == 0ull) return;
    int k;
    if (m0) { k = __ffsll((long long)m0) - 1;      m0 &= m0 - 1; }
    else    { k = 64 + __ffsll((long long)m1) - 1; m1 &= m1 - 1; }
    ulonglong2 v = W[k * 32 + lane];
    while (m0 | m1) {
        int kn;
        if (m0) { kn = __ffsll((long long)m0) - 1;      m0 &= m0 - 1; }
        else    { kn = 64 + __ffsll((long long)m1) - 1; m1 &= m1 - 1; }
        ulonglong2 vn = W[kn * 32 + lane];
        add2(a, v.x); add2(b, v.y);
        v = vn;
    }
    add2(a, v.x); add2(b, v.y);
}

#define RING_D 64

__global__ void __launch_bounds__(256, 1) k2_rec(
    const float* __restrict__ Wh1, const float* __restrict__ Wi2,
    const float* __restrict__ bi2, const float* __restrict__ Wh2,
    const float* __restrict__ bh2, const float* __restrict__ Wo,
    const float* __restrict__ bo, float* __restrict__ out)
{
    extern __shared__ float sm[];
    float* wh1s = sm;                 // 16384 f each, permuted like k1's ws
    float* wi2s = sm + 16384;
    float* wh2s = sm + 32768;
    ulonglong2* ringAll = (ulonglong2*)(sm + 49152);           // 4 rows x 64 x 16B
    unsigned* ctr = (unsigned*)((char*)(sm + 49152) + 4096);   // prod/cons, strided

    const int tid = threadIdx.x, lane = tid & 31, warp = tid >> 5;
    const int rl = warp & 3;                 // row local
    const int row = blockIdx.x * 4 + rl;
    ulonglong2* ring = ringAll + rl * RING_D;
    unsigned* prod = &ctr[rl * 16];
    unsigned* cons = &ctr[rl * 16 + 8];

    for (int i = tid; i < HD * HD; i += 256) {
        int j = i >> 7, k = i & 127;
        int d = k * 128 + ((j & 31) << 2) + (j >> 5);
        wh1s[d] = Wh1[i];
        wi2s[d] = Wi2[i];
        wh2s[d] = Wh2[i];
    }
    if (tid < 64) ctr[tid] = 0;
    __syncthreads();

    if (warp < 4) {
        // ---------------- producer: layer 1 ----------------
        const ulonglong2* W1 = (const ulonglong2*)wh1s;
        const float4* pre = (const float4*)g_pre1 + (size_t)row * TS * 32 + lane;

        ull s_lo = 0, s_hi = 0;
        unsigned consSeen = 0;

        float4 f0 = pre[0 * 32], f1 = pre[1 * 32], f2 = pre[2 * 32], f3 = pre[3 * 32];

        auto stepA = [&](const float4& cur, int t) {
            // backpressure: keep within ring (consumer publishes every 16 steps)
            if (consSeen + 40 < (unsigned)t) {
                do { consSeen = ld_acq(cons); } while (consSeen + 40 < (unsigned)t);
            }
            ull h01 = pk2(cur.x, cur.y), h23 = pk2(cur.z, cur.w);
            walk(W1, s_lo, s_hi, lane, h01, h23);
            const float2 ha = upk2(h01), hb = upk2(h23);
            unsigned q0 = __ballot_sync(0xffffffffu, ha.x >= 1.0f);
            unsigned q1 = __ballot_sync(0xffffffffu, ha.y >= 1.0f);
            unsigned q2 = __ballot_sync(0xffffffffu, hb.x >= 1.0f);
            unsigned q3 = __ballot_sync(0xffffffffu, hb.y >= 1.0f);
            s_lo = (ull)q0 | ((ull)q1 << 32);
            s_hi = (ull)q2 | ((ull)q3 << 32);
            if (lane == 0) {
                ulonglong2 m; m.x = s_lo; m.y = s_hi;
                ring[t & (RING_D - 1)] = m;
                st_rel(prod, (unsigned)(t + 1));
            }
        };

        for (int t = 0; t < TS; t += 4) {
            stepA(f0, t + 0); f0 = pre[(t + 4) * 32];
            stepA(f1, t + 1); f1 = pre[(t + 5) * 32];
            stepA(f2, t + 2); f2 = pre[(t + 6) * 32];
            stepA(f3, t + 3); f3 = pre[(t + 7) * 32];
        }
    } else {
        // ---------------- consumer: layer 2 + counts ----------------
        const ulonglong2* W2i = (const ulonglong2*)wi2s;
        const ulonglong2* W2h = (const ulonglong2*)wh2s;

        const ull b01 = pk2(bi2[lane]      + bh2[lane],      bi2[lane + 32] + bh2[lane + 32]);
        const ull b23 = pk2(bi2[lane + 64] + bh2[lane + 64], bi2[lane + 96] + bh2[lane + 96]);

        ull r2_lo = 0, r2_hi = 0;
        unsigned prodSeen = 0;
        int c0 = 0, c1 = 0, c2 = 0, c3 = 0;

        for (int t = 0; t < TS; ++t) {
            if (prodSeen <= (unsigned)t) {
                do { prodSeen = ld_acq(prod); } while (prodSeen <= (unsigned)t);
            }
            const ulonglong2 m = ring[t & (RING_D - 1)];   // broadcast read

            ull g01 = b01, g23 = b23;
            walk(W2i, m.x, m.y, lane, g01, g23);
            walk(W2h, r2_lo, r2_hi, lane, g01, g23);

            const float2 ga = upk2(g01), gb = upk2(g23);
            const bool p0 = (ga.x >= 1.0f), p1 = (ga.y >= 1.0f);
            const bool p2 = (gb.x >= 1.0f), p3 = (gb.y >= 1.0f);
            unsigned q0 = __ballot_sync(0xffffffffu, p0);
            unsigned q1 = __ballot_sync(0xffffffffu, p1);
            unsigned q2 = __ballot_sync(0xffffffffu, p2);
            unsigned q3 = __ballot_sync(0xffffffffu, p3);
            r2_lo = (ull)q0 | ((ull)q1 << 32);
            r2_hi = (ull)q2 | ((ull)q3 << 32);
            c0 += p0; c1 += p1; c2 += p2; c3 += p3;

            if (((t & 15) == 15) && lane == 0) st_rel(cons, (unsigned)(t + 1));
        }

        // epilogue: out[row] = bo + counts @ Wo^T / T
        const float f0 = (float)c0, f1 = (float)c1, f2 = (float)c2, f3 = (float)c3;
#pragma unroll
        for (int o = 0; o < DOUT; ++o) {
            const float* wr = Wo + o * HD;
            float p = f0 * wr[lane] + f1 * wr[lane + 32]
                    + f2 * wr[lane + 64] + f3 * wr[lane + 96];
#pragma unroll
            for (int s = 16; s; s >>= 1) p += __shfl_xor_sync(0xffffffffu, p, s);
            if (lane == 0) out[row * DOUT + o] = bo[o] + p * (1.0f / (float)TS);
        }
    }
}

extern "C" void kernel_launch(void* const* d_in, const int* in_sizes, int n_in,
                              void* d_out, int out_size)
{
    const float* x   = (const float*)d_in[0];
    const float* Wi1 = (const float*)d_in[1];
    const float* bi1 = (const float*)d_in[2];
    const float* Wh1 = (const float*)d_in[3];
    const float* bh1 = (const float*)d_in[4];
    const float* Wi2 = (const float*)d_in[5];
    const float* bi2 = (const float*)d_in[6];
    const float* Wh2 = (const float*)d_in[7];
    const float* bh2 = (const float*)d_in[8];
    const float* Wo  = (const float*)d_in[9];
    const float* bo  = (const float*)d_in[10];
    float* out = (float*)d_out;

    cudaFuncSetAttribute(k1_gemm, cudaFuncAttributeMaxDynamicSharedMemorySize, 98304);
    cudaFuncSetAttribute(k2_rec,  cudaFuncAttributeMaxDynamicSharedMemorySize, 201024);

    k1_gemm<<<MTOT / 32, 256, 98304>>>(x, Wi1, bi1, bh1);
    k2_rec<<<NB / 4, 256, 201024>>>(Wh1, Wi2, bi2, Wh2, bh2, Wo, bo, out);
}

// round 7
// speedup vs baseline: 1.0012x; 1.0012x over previous
#include <cuda_runtime.h>
#include <cuda_bf16.h>
#include <cstdint>
#include <cstddef>

// SRNN_multi: 2-layer spiking RNN, N=512, T=1000, H=128, DOUT=20.
//   prep: permute all recurrent/input weight matrices once into gmem
//   k1:   pre1[n,t,:] = x[n,t,:] @ Wi1^T + bi1 + bh1     (time-parallel GEMM)
//   k2a:  s1(t) = [pre1_t + s1@Wh1^T >= 1]  -> mask stream to gmem (512 rows par.)
//   k2b:  s2(t) = [s1@Wi2^T + b2 + s2@Wh2^T >= 1]; counts; out epilogue
//   out = bo + (sum_t s2) @ Wo^T / T

#define NB   512
#define TS   1000
#define HD   128
#define DOUT 20
#define MTOT (NB * TS)
#define XS   66          // xT k-stride in floats (even, keeps 8B alignment, low STS conflicts)

typedef unsigned long long ull;

// pre1 scratch, permuted: g_pre1[row*128 + lane*4 + q] = pre1[row][lane + 32*q]
// +2048 pad: k2a prefetches up to 15 steps past the last row.
__device__ float g_pre1[(size_t)MTOT * HD + 2048];
// s1 spike masks per (row, t): two 64-bit words (k 0-63, 64-127)
__device__ ulonglong2 g_s1[(size_t)NB * TS + 16];
// permuted weights: P[k*128 + (j&31)*4 + (j>>5)] = W[j*128 + k]
__device__ float g_Wi1p[HD * HD], g_Wh1p[HD * HD], g_Wi2p[HD * HD], g_Wh2p[HD * HD];

__device__ __forceinline__ ull pk2(float lo, float hi) {
    ull r; asm("mov.b64 %0, {%1, %2};" : "=l"(r) : "f"(lo), "f"(hi)); return r;
}
__device__ __forceinline__ float2 upk2(ull v) {
    float2 r; asm("mov.b64 {%0, %1}, %2;" : "=f"(r.x), "=f"(r.y) : "l"(v)); return r;
}
__device__ __forceinline__ void fma2(ull& d, ull a, ull b) {
    asm("fma.rn.f32x2 %0, %1, %2, %0;" : "+l"(d) : "l"(a), "l"(b));
}
__device__ __forceinline__ void add2(ull& d, ull a) {
    asm("add.rn.f32x2 %0, %1, %0;" : "+l"(d) : "l"(a));
}

// ---------------------------------------------------------------------------
// prep: one-time weight permutation (coalesced reads, scattered 4B writes).
// ---------------------------------------------------------------------------
__global__ void prep(const float* __restrict__ Wi1, const float* __restrict__ Wh1,
                     const float* __restrict__ Wi2, const float* __restrict__ Wh2)
{
    int i = blockIdx.x * blockDim.x + threadIdx.x;
    if (i < HD * HD) {
        int j = i >> 7, k = i & 127;
        int d = k * 128 + ((j & 31) << 2) + (j >> 5);
        g_Wi1p[d] = Wi1[i];
        g_Wh1p[d] = Wh1[i];
        g_Wi2p[d] = Wi2[i];
        g_Wh2p[d] = Wh2[i];
    }
}

// ---------------------------------------------------------------------------
// Kernel 1: pre1 = x @ Wi1^T + (bi1+bh1).
// 8000 CTAs x 256 thr; CTA = 64 rows; warp = 8 rows (4 row-pairs) x 128 cols.
// Row-pair packed accumulators: acc[q][p] = (sum row 2p, sum row 2p+1) for
// col lane+32q. Multiplier = x pair from transposed smem (broadcast LDS.64);
// multiplicand = duplicated weight (4 MOVs per k, amortized over 8 rows).
// ---------------------------------------------------------------------------
__global__ void __launch_bounds__(256, 2) k1_gemm(
    const float* __restrict__ x, const float* __restrict__ bi1,
    const float* __restrict__ bh1)
{
    extern __shared__ float sm[];
    float* ws = sm;            // 16384 f: permuted Wi1 (straight copy of g_Wi1p)
    float* xT = sm + 16384;    // 128*XS f: xT[k*XS + r] = x[row_base+r][k]

    const int tid = threadIdx.x, lane = tid & 31, warp = tid >> 5;

    // stage permuted Wi1: conflict-free float4 copy
    {
        const float4* Wp = (const float4*)g_Wi1p;
        float4* w4 = (float4*)ws;
        for (int i = tid; i < 4096; i += 256) w4[i] = Wp[i];
    }
    // stage x transposed: coalesced LDG.128, scattered STS (bounded conflicts)
    {
        const float4* xg = (const float4*)x + (size_t)blockIdx.x * 2048;
        for (int i = tid; i < 2048; i += 256) {
            float4 v = xg[i];
            int r = i >> 5, c = (i & 31) << 2;
            xT[(c + 0) * XS + r] = v.x;
            xT[(c + 1) * XS + r] = v.y;
            xT[(c + 2) * XS + r] = v.z;
            xT[(c + 3) * XS + r] = v.w;
        }
    }
    __syncthreads();

    // bias (per column, duplicated across the row pair)
    ull acc[4][4];
#pragma unroll
    for (int q = 0; q < 4; ++q) {
        const float b = bi1[lane + 32 * q] + bh1[lane + 32 * q];
        const ull bd = pk2(b, b);
#pragma unroll
        for (int p = 0; p < 4; ++p) acc[q][p] = bd;
    }

    const float4* W4 = (const float4*)ws;      // W4[k*32 + lane] = cols {l,l+32,l+64,l+96}
    const float* xw = xT + warp * 8;

#pragma unroll 4
    for (int k = 0; k < 128; ++k) {
        const float4 wv = W4[k * 32 + lane];
        const ull wd0 = pk2(wv.x, wv.x), wd1 = pk2(wv.y, wv.y);
        const ull wd2 = pk2(wv.z, wv.z), wd3 = pk2(wv.w, wv.w);
        const ull* xp = (const ull*)(xw + k * XS);   // 4 row-pairs, warp-uniform
#pragma unroll
        for (int p = 0; p < 4; ++p) {
            const ull xv = xp[p];
            fma2(acc[0][p], xv, wd0);
            fma2(acc[1][p], xv, wd1);
            fma2(acc[2][p], xv, wd2);
            fma2(acc[3][p], xv, wd3);
        }
    }

    const size_t rbase = (size_t)blockIdx.x * 64 + warp * 8;
#pragma unroll
    for (int p = 0; p < 4; ++p) {
        const float2 a0 = upk2(acc[0][p]), a1 = upk2(acc[1][p]);
        const float2 a2 = upk2(acc[2][p]), a3 = upk2(acc[3][p]);
        float4 e; e.x = a0.x; e.y = a1.x; e.z = a2.x; e.w = a3.x;
        float4 o; o.x = a0.y; o.y = a1.y; o.z = a2.y; o.w = a3.y;
        *(float4*)(g_pre1 + (rbase + 2 * p)     * 128 + lane * 4) = e;
        *(float4*)(g_pre1 + (rbase + 2 * p + 1) * 128 + lane * 4) = o;
    }
}

// ---------------------------------------------------------------------------
// Sparse accumulate: ascending-k walk over a 128-bit mask (two 64-bit words),
// software-pipelined (next column loaded before current is accumulated).
// Identical accumulation order to previous rounds.
// ---------------------------------------------------------------------------
__device__ __forceinline__ void walk(
    const ulonglong2* __restrict__ W, ull m0, ull m1, int lane, ull& a, ull& b)
{
    if ((m0 | m1) == 0ull) return;
    int k;
    if (m0) { k = __ffsll((long long)m0) - 1;      m0 &= m0 - 1; }
    else    { k = 64 + __ffsll((long long)m1) - 1; m1 &= m1 - 1; }
    ulonglong2 v = W[k * 32 + lane];
    while (m0 | m1) {
        int kn;
        if (m0) { kn = __ffsll((long long)m0) - 1;      m0 &= m0 - 1; }
        else    { kn = 64 + __ffsll((long long)m1) - 1; m1 &= m1 - 1; }
        ulonglong2 vn = W[kn * 32 + lane];
        add2(a, v.x); add2(b, v.y);
        v = vn;
    }
    add2(a, v.x); add2(b, v.y);
}

// predicated lane-0 mask store (no BSSY/BSYNC)
__device__ __forceinline__ void stg_mask(ulonglong2* p, ull lo, ull hi, int lane) {
    asm volatile(
        "{\n\t.reg .pred p0;\n\tsetp.eq.s32 p0, %0, 0;\n\t"
        "@p0 st.global.v2.u64 [%1], {%2, %3};\n\t}"
        :: "r"(lane), "l"(p), "l"(lo), "l"(hi) : "memory");
}

// ---------------------------------------------------------------------------
// Kernel 2a: layer-1 recurrence. 512 CTAs x 32 thr (warp = row).
// Weights via L1-resident permuted gmem. pre1 prefetched 8 steps deep.
// ---------------------------------------------------------------------------
__global__ void __launch_bounds__(32) k2a(void)
{
    const int lane = threadIdx.x;
    const int row  = blockIdx.x;
    const ulonglong2* W1 = (const ulonglong2*)(const void*)g_Wh1p;
    const float4* pre = (const float4*)g_pre1 + (size_t)row * TS * 32 + lane;
    ulonglong2* ms = g_s1 + (size_t)row * TS;

    ull s_lo = 0, s_hi = 0;

    float4 f0 = pre[0 * 32], f1 = pre[1 * 32], f2 = pre[2 * 32], f3 = pre[3 * 32];
    float4 f4 = pre[4 * 32], f5 = pre[5 * 32], f6 = pre[6 * 32], f7 = pre[7 * 32];

    auto step = [&](const float4& cur, int t) {
        ull h01 = pk2(cur.x, cur.y), h23 = pk2(cur.z, cur.w);
        walk(W1, s_lo, s_hi, lane, h01, h23);
        const float2 ha = upk2(h01), hb = upk2(h23);
        const unsigned q0 = __ballot_sync(0xffffffffu, ha.x >= 1.0f);
        const unsigned q1 = __ballot_sync(0xffffffffu, ha.y >= 1.0f);
        const unsigned q2 = __ballot_sync(0xffffffffu, hb.x >= 1.0f);
        const unsigned q3 = __ballot_sync(0xffffffffu, hb.y >= 1.0f);
        s_lo = (ull)q0 | ((ull)q1 << 32);
        s_hi = (ull)q2 | ((ull)q3 << 32);
        stg_mask(ms + t, s_lo, s_hi, lane);
    };

    for (int t = 0; t < TS; t += 8) {
        step(f0, t + 0); f0 = pre[(t +  8) * 32];
        step(f1, t + 1); f1 = pre[(t +  9) * 32];
        step(f2, t + 2); f2 = pre[(t + 10) * 32];
        step(f3, t + 3); f3 = pre[(t + 11) * 32];
        step(f4, t + 4); f4 = pre[(t + 12) * 32];
        step(f5, t + 5); f5 = pre[(t + 13) * 32];
        step(f6, t + 6); f6 = pre[(t + 14) * 32];
        step(f7, t + 7); f7 = pre[(t + 15) * 32];
    }
}

// ---------------------------------------------------------------------------
// Kernel 2b: layer-2 recurrence + spike counts + output. 512 CTAs x 32 thr.
// Masks prefetched 8 deep (pure data), weights via L1-resident gmem.
// ---------------------------------------------------------------------------
__global__ void __launch_bounds__(32) k2b(
    const float* __restrict__ bi2, const float* __restrict__ bh2,
    const float* __restrict__ Wo,  const float* __restrict__ bo,
    float* __restrict__ out)
{
    const int lane = threadIdx.x;
    const int row  = blockIdx.x;
    const ulonglong2* W2i = (const ulonglong2*)(const void*)g_Wi2p;
    const ulonglong2* W2h = (const ulonglong2*)(const void*)g_Wh2p;
    const ulonglong2* ms  = g_s1 + (size_t)row * TS;

    const ull b01 = pk2(bi2[lane]      + bh2[lane],      bi2[lane + 32] + bh2[lane + 32]);
    const ull b23 = pk2(bi2[lane + 64] + bh2[lane + 64], bi2[lane + 96] + bh2[lane + 96]);

    ull r2_lo = 0, r2_hi = 0;
    int c0 = 0, c1 = 0, c2 = 0, c3 = 0;

    ulonglong2 m0 = ms[0], m1 = ms[1], m2 = ms[2], m3 = ms[3];
    ulonglong2 m4 = ms[4], m5 = ms[5], m6 = ms[6], m7 = ms[7];

    auto stepB = [&](const ulonglong2& m) {
        ull g01 = b01, g23 = b23;
        walk(W2i, m.x,   m.y,   lane, g01, g23);
        walk(W2h, r2_lo, r2_hi, lane, g01, g23);
        const float2 ga = upk2(g01), gb = upk2(g23);
        const bool p0 = (ga.x >= 1.0f), p1 = (ga.y >= 1.0f);
        const bool p2 = (gb.x >= 1.0f), p3 = (gb.y >= 1.0f);
        const unsigned q0 = __ballot_sync(0xffffffffu, p0);
        const unsigned q1 = __ballot_sync(0xffffffffu, p1);
        const unsigned q2 = __ballot_sync(0xffffffffu, p2);
        const unsigned q3 = __ballot_sync(0xffffffffu, p3);
        r2_lo = (ull)q0 | ((ull)q1 << 32);
        r2_hi = (ull)q2 | ((ull)q3 << 32);
        c0 += p0; c1 += p1; c2 += p2; c3 += p3;
    };

    for (int t = 0; t < TS; t += 8) {
        const int lim = TS - 1;
        stepB(m0); m0 = ms[min(t +  8, lim)];
        stepB(m1); m1 = ms[min(t +  9, lim)];
        stepB(m2); m2 = ms[min(t + 10, lim)];
        stepB(m3); m3 = ms[min(t + 11, lim)];
        stepB(m4); m4 = ms[min(t + 12, lim)];
        stepB(m5); m5 = ms[min(t + 13, lim)];
        stepB(m6); m6 = ms[min(t + 14, lim)];
        stepB(m7); m7 = ms[min(t + 15, lim)];
    }

    // out[row] = bo + counts @ Wo^T / T
    const float f0 = (float)c0, f1 = (float)c1, f2 = (float)c2, f3 = (float)c3;
#pragma unroll
    for (int o = 0; o < DOUT; ++o) {
        const float* wr = Wo + o * HD;
        float p = f0 * wr[lane] + f1 * wr[lane + 32]
                + f2 * wr[lane + 64] + f3 * wr[lane + 96];
#pragma unroll
        for (int s = 16; s; s >>= 1) p += __shfl_xor_sync(0xffffffffu, p, s);
        if (lane == 0) out[row * DOUT + o] = bo[o] + p * (1.0f / (float)TS);
    }
}

extern "C" void kernel_launch(void* const* d_in, const int* in_sizes, int n_in,
                              void* d_out, int out_size)
{
    const float* x   = (const float*)d_in[0];
    const float* Wi1 = (const float*)d_in[1];
    const float* bi1 = (const float*)d_in[2];
    const float* Wh1 = (const float*)d_in[3];
    const float* bh1 = (const float*)d_in[4];
    const float* Wi2 = (const float*)d_in[5];
    const float* bi2 = (const float*)d_in[6];
    const float* Wh2 = (const float*)d_in[7];
    const float* bh2 = (const float*)d_in[8];
    const float* Wo  = (const float*)d_in[9];
    const float* bo  = (const float*)d_in[10];
    float* out = (float*)d_out;

    const int k1_smem = (16384 + 128 * XS) * 4;   // 99328 B -> 2 CTAs/SM
    cudaFuncSetAttribute(k1_gemm, cudaFuncAttributeMaxDynamicSharedMemorySize, k1_smem);

    prep<<<64, 256>>>(Wi1, Wh1, Wi2, Wh2);
    k1_gemm<<<MTOT / 64, 256, k1_smem>>>(x, bi1, bh1);
    k2a<<<NB, 32>>>();
    k2b<<<NB, 32>>>(bi2, bh2, Wo, bo, out);
}

// round 10
// speedup vs baseline: 1.7771x; 1.7750x over previous
#include <cuda_runtime.h>
#include <cuda_bf16.h>
#include <cstdint>
#include <cstddef>

// SRNN_multi: 2-layer spiking RNN, N=512, T=1000, H=128, DOUT=20.
//   prep:  permute weight matrices once into gmem
//   k1:    pre1[n,t,:] = x[n,t,:] @ Wi1^T + bi1 + bh1    (time-parallel GEMM)
//   k2a:   s1(t) = [pre1_t + s1@Wh1^T >= 1] -> mask stream (recurrent, 512 warps)
//   k2b1:  gi(row,t) = b2 + s1(t)@Wi2^T                  (parallel over all (row,t))
//   k2b2:  s2(t) = [gi_t + s2@Wh2^T >= 1]; counts        (recurrent, near-trivial)
//   out = bo + (sum_t s2) @ Wo^T / T

#define NB   512
#define TS   1000
#define HD   128
#define DOUT 20
#define MTOT (NB * TS)
#define XS   66

typedef unsigned long long ull;

// pre1 scratch, permuted: [(row*TS+t)*128 + lane*4 + q] = val[lane + 32*q].
// Reused by k2b1 as gi storage (k2a has fully consumed pre1 by then).
// +2048 pad: recurrent kernels prefetch up to 15 steps past the end.
__device__ float g_pre1[(size_t)MTOT * HD + 2048];
// s1 spike masks per (row,t): two 64-bit words (k 0-63, 64-127)
__device__ ulonglong2 g_s1[(size_t)NB * TS + 16];
// permuted weights: P[k*128 + (j&31)*4 + (j>>5)] = W[j*128 + k]
__device__ float g_Wi1p[HD * HD], g_Wh1p[HD * HD], g_Wi2p[HD * HD], g_Wh2p[HD * HD];

__device__ __forceinline__ ull pk2(float lo, float hi) {
    ull r; asm("mov.b64 %0, {%1, %2};" : "=l"(r) : "f"(lo), "f"(hi)); return r;
}
__device__ __forceinline__ float2 upk2(ull v) {
    float2 r; asm("mov.b64 {%0, %1}, %2;" : "=f"(r.x), "=f"(r.y) : "l"(v)); return r;
}
__device__ __forceinline__ void fma2(ull& d, ull a, ull b) {
    asm("fma.rn.f32x2 %0, %1, %2, %0;" : "+l"(d) : "l"(a), "l"(b));
}
__device__ __forceinline__ void add2(ull& d, ull a) {
    asm("add.rn.f32x2 %0, %1, %0;" : "+l"(d) : "l"(a));
}

// ---------------------------------------------------------------------------
// prep: one-time weight permutation.
// ---------------------------------------------------------------------------
__global__ void prep(const float* __restrict__ Wi1, const float* __restrict__ Wh1,
                     const float* __restrict__ Wi2, const float* __restrict__ Wh2)
{
    int i = blockIdx.x * blockDim.x + threadIdx.x;
    if (i < HD * HD) {
        int j = i >> 7, k = i & 127;
        int d = k * 128 + ((j & 31) << 2) + (j >> 5);
        g_Wi1p[d] = Wi1[i];
        g_Wh1p[d] = Wh1[i];
        g_Wi2p[d] = Wi2[i];
        g_Wh2p[d] = Wh2[i];
    }
}

// ---------------------------------------------------------------------------
// Kernel 1: pre1 = x @ Wi1^T + (bi1+bh1). (unchanged, known-good)
// ---------------------------------------------------------------------------
__global__ void __launch_bounds__(256, 2) k1_gemm(
    const float* __restrict__ x, const float* __restrict__ bi1,
    const float* __restrict__ bh1)
{
    extern __shared__ float sm[];
    float* ws = sm;            // 16384 f: permuted Wi1
    float* xT = sm + 16384;    // 128*XS f: xT[k*XS + r]

    const int tid = threadIdx.x, lane = tid & 31, warp = tid >> 5;

    {
        const float4* Wp = (const float4*)g_Wi1p;
        float4* w4 = (float4*)ws;
        for (int i = tid; i < 4096; i += 256) w4[i] = Wp[i];
    }
    {
        const float4* xg = (const float4*)x + (size_t)blockIdx.x * 2048;
        for (int i = tid; i < 2048; i += 256) {
            float4 v = xg[i];
            int r = i >> 5, c = (i & 31) << 2;
            xT[(c + 0) * XS + r] = v.x;
            xT[(c + 1) * XS + r] = v.y;
            xT[(c + 2) * XS + r] = v.z;
            xT[(c + 3) * XS + r] = v.w;
        }
    }
    __syncthreads();

    ull acc[4][4];
#pragma unroll
    for (int q = 0; q < 4; ++q) {
        const float b = bi1[lane + 32 * q] + bh1[lane + 32 * q];
        const ull bd = pk2(b, b);
#pragma unroll
        for (int p = 0; p < 4; ++p) acc[q][p] = bd;
    }

    const float4* W4 = (const float4*)ws;
    const float* xw = xT + warp * 8;

#pragma unroll 4
    for (int k = 0; k < 128; ++k) {
        const float4 wv = W4[k * 32 + lane];
        const ull wd0 = pk2(wv.x, wv.x), wd1 = pk2(wv.y, wv.y);
        const ull wd2 = pk2(wv.z, wv.z), wd3 = pk2(wv.w, wv.w);
        const ull* xp = (const ull*)(xw + k * XS);
#pragma unroll
        for (int p = 0; p < 4; ++p) {
            const ull xv = xp[p];
            fma2(acc[0][p], xv, wd0);
            fma2(acc[1][p], xv, wd1);
            fma2(acc[2][p], xv, wd2);
            fma2(acc[3][p], xv, wd3);
        }
    }

    const size_t rbase = (size_t)blockIdx.x * 64 + warp * 8;
#pragma unroll
    for (int p = 0; p < 4; ++p) {
        const float2 a0 = upk2(acc[0][p]), a1 = upk2(acc[1][p]);
        const float2 a2 = upk2(acc[2][p]), a3 = upk2(acc[3][p]);
        float4 e; e.x = a0.x; e.y = a1.x; e.z = a2.x; e.w = a3.x;
        float4 o; o.x = a0.y; o.y = a1.y; o.z = a2.y; o.w = a3.y;
        *(float4*)(g_pre1 + (rbase + 2 * p)     * 128 + lane * 4) = e;
        *(float4*)(g_pre1 + (rbase + 2 * p + 1) * 128 + lane * 4) = o;
    }
}

// ---------------------------------------------------------------------------
// Branchless next-set-bit over a 128-bit mask (ascending k), SEL-based.
// ---------------------------------------------------------------------------
__device__ __forceinline__ int nextbit(ull& m0, ull& m1) {
    const bool lo = (m0 != 0ull);
    const ull  w  = lo ? m0 : m1;
    const ull  wc = w & (w - 1);
    const int  k  = (lo ? 0 : 64) + __ffsll((long long)w) - 1;
    m0 = lo ? wc : m0;
    m1 = lo ? m1 : wc;
    return k;
}

// Fixed-trip-count, depth-2 software-pipelined sparse accumulate from smem.
// Accumulation order: ascending k (identical to previous rounds).
__device__ __forceinline__ void walkp(
    const ulonglong2* __restrict__ W, ull m0, ull m1, int lane, ull& a, ull& b)
{
    int n = __popcll(m0) + __popcll(m1);
    if (n == 0) return;
    ulonglong2 va = W[nextbit(m0, m1) * 32 + lane];
    if (n >= 2) {
        ulonglong2 vb = W[nextbit(m0, m1) * 32 + lane];
        for (int i = 2; i < n; ++i) {
            ulonglong2 vc = W[nextbit(m0, m1) * 32 + lane];
            add2(a, va.x); add2(b, va.y);
            va = vb; vb = vc;
        }
        add2(a, va.x); add2(b, va.y);
        va = vb;
    }
    add2(a, va.x); add2(b, va.y);
}

// predicated lane-0 store (no BSSY/BSYNC)
__device__ __forceinline__ void stg_mask(ulonglong2* p, ull lo, ull hi, int lane) {
    asm volatile(
        "{\n\t.reg .pred p0;\n\tsetp.eq.s32 p0, %0, 0;\n\t"
        "@p0 st.global.v2.u64 [%1], {%2, %3};\n\t}"
        :: "r"(lane), "l"(p), "l"(lo), "l"(hi) : "memory");
}

// ---------------------------------------------------------------------------
// Kernel 2a: layer-1 recurrence. 256 CTAs x 64 thr (2 rows/CTA).
// ---------------------------------------------------------------------------
__global__ void __launch_bounds__(64) k2a(void)
{
    extern __shared__ float sm[];      // 16384 f = permuted Wh1
    const int tid = threadIdx.x, lane = tid & 31, warp = tid >> 5;

    {
        const float4* Wp = (const float4*)g_Wh1p;
        float4* w4 = (float4*)sm;
        for (int i = tid; i < 4096; i += 64) w4[i] = Wp[i];
    }
    __syncthreads();

    const ulonglong2* W1 = (const ulonglong2*)sm;
    const int row = blockIdx.x * 2 + warp;
    const float4* pre = (const float4*)g_pre1 + (size_t)row * TS * 32 + lane;
    ulonglong2* ms = g_s1 + (size_t)row * TS;

    ull s_lo = 0, s_hi = 0;

    float4 f0 = pre[0 * 32], f1 = pre[1 * 32], f2 = pre[2 * 32], f3 = pre[3 * 32];
    float4 f4 = pre[4 * 32], f5 = pre[5 * 32], f6 = pre[6 * 32], f7 = pre[7 * 32];

    auto step = [&](const float4& cur, int t) {
        ull h01 = pk2(cur.x, cur.y), h23 = pk2(cur.z, cur.w);
        walkp(W1, s_lo, s_hi, lane, h01, h23);
        const float2 ha = upk2(h01), hb = upk2(h23);
        const unsigned q0 = __ballot_sync(0xffffffffu, ha.x >= 1.0f);
        const unsigned q1 = __ballot_sync(0xffffffffu, ha.y >= 1.0f);
        const unsigned q2 = __ballot_sync(0xffffffffu, hb.x >= 1.0f);
        const unsigned q3 = __ballot_sync(0xffffffffu, hb.y >= 1.0f);
        s_lo = (ull)q0 | ((ull)q1 << 32);
        s_hi = (ull)q2 | ((ull)q3 << 32);
        stg_mask(ms + t, s_lo, s_hi, lane);
    };

    for (int t = 0; t < TS; t += 8) {
        step(f0, t + 0); f0 = pre[(t +  8) * 32];
        step(f1, t + 1); f1 = pre[(t +  9) * 32];
        step(f2, t + 2); f2 = pre[(t + 10) * 32];
        step(f3, t + 3); f3 = pre[(t + 11) * 32];
        step(f4, t + 4); f4 = pre[(t + 12) * 32];
        step(f5, t + 5); f5 = pre[(t + 13) * 32];
        step(f6, t + 6); f6 = pre[(t + 14) * 32];
        step(f7, t + 7); f7 = pre[(t + 15) * 32];
    }
}

// ---------------------------------------------------------------------------
// Kernel 2b1: gi(row,t) = b2 + s1(t)@Wi2^T, parallel over all 512000 (row,t).
// 256 CTAs x 256 thr = 2048 warps; warp w: row = w>>2, t-strip = (w&3)*250.
// Writes gi into g_pre1 (reused; k2a already consumed pre1).
// FIX vs R8/R9: per-t slot is 32 ulonglong2 (128 floats = 512 B), not 8 —
// both the row base and the t stride were 4x too small, overlapping lanes
// across timesteps (caused rel_err 0.47).
// ---------------------------------------------------------------------------
__global__ void __launch_bounds__(256) k2b1(
    const float* __restrict__ bi2, const float* __restrict__ bh2)
{
    extern __shared__ float sm[];      // 16384 f = permuted Wi2
    const int tid = threadIdx.x, lane = tid & 31;

    {
        const float4* Wp = (const float4*)g_Wi2p;
        float4* w4 = (float4*)sm;
        for (int i = tid; i < 4096; i += 256) w4[i] = Wp[i];
    }
    __syncthreads();

    const ulonglong2* W2i = (const ulonglong2*)sm;
    const int w    = blockIdx.x * 8 + (tid >> 5);
    const int row  = w >> 2;
    const int t0   = (w & 3) * (TS / 4);
    const int t1   = t0 + (TS / 4);

    const ull b01 = pk2(bi2[lane]      + bh2[lane],      bi2[lane + 32] + bh2[lane + 32]);
    const ull b23 = pk2(bi2[lane + 64] + bh2[lane + 64], bi2[lane + 96] + bh2[lane + 96]);

    const ulonglong2* ms = g_s1 + (size_t)row * TS;
    ulonglong2* gi = (ulonglong2*)g_pre1 + (size_t)row * TS * 32 + lane;

    ulonglong2 mA = ms[t0], mB = ms[t0 + 1];
    for (int t = t0; t < t1; ++t) {
        const ulonglong2 m = mA;
        mA = mB;
        mB = ms[min(t + 2, t1 - 1)];
        ull g01 = b01, g23 = b23;
        walkp(W2i, m.x, m.y, lane, g01, g23);
        ulonglong2 o; o.x = g01; o.y = g23;
        gi[(size_t)t * 32] = o;     // float4 {g_l, g_l+32, g_l+64, g_l+96}
    }
}

// ---------------------------------------------------------------------------
// Kernel 2b2: layer-2 recurrence + counts + output. 256 CTAs x 64 thr.
// ---------------------------------------------------------------------------
__global__ void __launch_bounds__(64) k2b2(
    const float* __restrict__ Wo, const float* __restrict__ bo,
    float* __restrict__ out)
{
    extern __shared__ float sm[];      // 16384 f = permuted Wh2
    const int tid = threadIdx.x, lane = tid & 31, warp = tid >> 5;

    {
        const float4* Wp = (const float4*)g_Wh2p;
        float4* w4 = (float4*)sm;
        for (int i = tid; i < 4096; i += 64) w4[i] = Wp[i];
    }
    __syncthreads();

    const ulonglong2* W2h = (const ulonglong2*)sm;
    const int row = blockIdx.x * 2 + warp;
    const float4* gi = (const float4*)g_pre1 + (size_t)row * TS * 32 + lane;

    ull r2_lo = 0, r2_hi = 0;
    int c0 = 0, c1 = 0, c2 = 0, c3 = 0;

    float4 f0 = gi[0 * 32], f1 = gi[1 * 32], f2 = gi[2 * 32], f3 = gi[3 * 32];
    float4 f4 = gi[4 * 32], f5 = gi[5 * 32], f6 = gi[6 * 32], f7 = gi[7 * 32];

    auto stepB = [&](const float4& cur) {
        ull g01 = pk2(cur.x, cur.y), g23 = pk2(cur.z, cur.w);
        walkp(W2h, r2_lo, r2_hi, lane, g01, g23);
        const float2 ga = upk2(g01), gb = upk2(g23);
        const bool p0 = (ga.x >= 1.0f), p1 = (ga.y >= 1.0f);
        const bool p2 = (gb.x >= 1.0f), p3 = (gb.y >= 1.0f);
        const unsigned q0 = __ballot_sync(0xffffffffu, p0);
        const unsigned q1 = __ballot_sync(0xffffffffu, p1);
        const unsigned q2 = __ballot_sync(0xffffffffu, p2);
        const unsigned q3 = __ballot_sync(0xffffffffu, p3);
        r2_lo = (ull)q0 | ((ull)q1 << 32);
        r2_hi = (ull)q2 | ((ull)q3 << 32);
        c0 += p0; c1 += p1; c2 += p2; c3 += p3;
    };

    for (int t = 0; t < TS; t += 8) {
        stepB(f0); f0 = gi[(t +  8) * 32];
        stepB(f1); f1 = gi[(t +  9) * 32];
        stepB(f2); f2 = gi[(t + 10) * 32];
        stepB(f3); f3 = gi[(t + 11) * 32];
        stepB(f4); f4 = gi[(t + 12) * 32];
        stepB(f5); f5 = gi[(t + 13) * 32];
        stepB(f6); f6 = gi[(t + 14) * 32];
        stepB(f7); f7 = gi[(t + 15) * 32];
    }

    // out[row] = bo + counts @ Wo^T / T
    const float f0c = (float)c0, f1c = (float)c1, f2c = (float)c2, f3c = (float)c3;
#pragma unroll
    for (int o = 0; o < DOUT; ++o) {
        const float* wr = Wo + o * HD;
        float p = f0c * wr[lane] + f1c * wr[lane + 32]
                + f2c * wr[lane + 64] + f3c * wr[lane + 96];
#pragma unroll
        for (int s = 16; s; s >>= 1) p += __shfl_xor_sync(0xffffffffu, p, s);
        if (lane == 0) out[row * DOUT + o] = bo[o] + p * (1.0f / (float)TS);
    }
}

extern "C" void kernel_launch(void* const* d_in, const int* in_sizes, int n_in,
                              void* d_out, int out_size)
{
    const float* x   = (const float*)d_in[0];
    const float* Wi1 = (const float*)d_in[1];
    const float* bi1 = (const float*)d_in[2];
    const float* Wh1 = (const float*)d_in[3];
    const float* bh1 = (const float*)d_in[4];
    const float* Wi2 = (const float*)d_in[5];
    const float* bi2 = (const float*)d_in[6];
    const float* Wh2 = (const float*)d_in[7];
    const float* bh2 = (const float*)d_in[8];
    const float* Wo  = (const float*)d_in[9];
    const float* bo  = (const float*)d_in[10];
    float* out = (float*)d_out;

    const int k1_smem = (16384 + 128 * XS) * 4;   // 99328 B
    const int w_smem  = 16384 * 4;                // 65536 B
    cudaFuncSetAttribute(k1_gemm, cudaFuncAttributeMaxDynamicSharedMemorySize, k1_smem);
    cudaFuncSetAttribute(k2a,  cudaFuncAttributeMaxDynamicSharedMemorySize, w_smem);
    cudaFuncSetAttribute(k2b1, cudaFuncAttributeMaxDynamicSharedMemorySize, w_smem);
    cudaFuncSetAttribute(k2b2, cudaFuncAttributeMaxDynamicSharedMemorySize, w_smem);

    prep<<<64, 256>>>(Wi1, Wh1, Wi2, Wh2);
    k1_gemm<<<MTOT / 64, 256, k1_smem>>>(x, bi1, bh1);
    k2a<<<NB / 2, 64, w_smem>>>();
    k2b1<<<256, 256, w_smem>>>(bi2, bh2);
    k2b2<<<NB / 2, 64, w_smem>>>(Wo, bo, out);
}